// round 3
// baseline (speedup 1.0000x reference)
#include <cuda_runtime.h>
#include <cuda_bf16.h>
#include <math.h>
#include <stdint.h>

// ---------------- problem constants ----------------
#define NN   50000   // nodes
#define EE   400000  // edges per relation
#define RR   3       // relations
#define FIN  128     // input features
#define FHID 64      // hidden features
#define FC   40      // classes
#define NH   3       // heads
#define NEG_SLOPE 0.2f

#define SCRATCH_BYTES (320ull * 1024 * 1024)
__device__ __align__(256) unsigned char g_scratch[SCRATCH_BYTES];

__device__ __forceinline__ float lrelu(float x) { return x > 0.f ? x : NEG_SLOPE * x; }

// ---------------- CSR build ----------------
__global__ void zero_k(int* p, int nitems) {
    int i = blockIdx.x * blockDim.x + threadIdx.x;
    if (i < nitems) p[i] = 0;
}

__global__ void count_k(const int* __restrict__ dst, int* __restrict__ cnt) {
    int i = blockIdx.x * blockDim.x + threadIdx.x;
    if (i >= RR * EE) return;
    int r = i / EE;
    atomicAdd(&cnt[r * NN + dst[i]], 1);
}

__global__ void scan_k(const int* __restrict__ cnt, int* __restrict__ ptr, int* __restrict__ cur) {
    const int r = blockIdx.x;
    const int t = threadIdx.x;
    const int CH = (NN + 1023) / 1024;
    int s0 = t * CH;
    int s1 = s0 + CH; if (s1 > NN) s1 = NN;
    if (s0 > NN) s0 = NN;
    int sum = 0;
    for (int n = s0; n < s1; n++) sum += cnt[r * NN + n];
    __shared__ int sh[1024];
    sh[t] = sum;
    __syncthreads();
    for (int off = 1; off < 1024; off <<= 1) {
        int v = (t >= off) ? sh[t - off] : 0;
        __syncthreads();
        sh[t] += v;
        __syncthreads();
    }
    int base = sh[t] - sum;
    for (int n = s0; n < s1; n++) {
        ptr[r * (NN + 1) + n] = base;
        cur[r * NN + n] = base;
        base += cnt[r * NN + n];
    }
    if (t == 1023) ptr[r * (NN + 1) + NN] = sh[1023];
}

__global__ void scatter_k(const int* __restrict__ src, const int* __restrict__ dst,
                          int* __restrict__ cur, int* __restrict__ csrc,
                          int* __restrict__ cdst) {
    int i = blockIdx.x * blockDim.x + threadIdx.x;
    if (i >= RR * EE) return;
    int r = i / EE;
    int d = dst[i];
    int pos = atomicAdd(&cur[r * NN + d], 1);
    csrc[(size_t)r * EE + pos] = src[i];
    cdst[(size_t)r * EE + pos] = d;
}

// ---------------- fp32 -> (bf16 hi, bf16 lo) split ----------------
__global__ void split_k(const float* __restrict__ in, __nv_bfloat16* __restrict__ hi,
                        __nv_bfloat16* __restrict__ lo, int n4) {
    int i = blockIdx.x * blockDim.x + threadIdx.x;
    if (i >= n4) return;
    float4 v = ((const float4*)in)[i];
    __nv_bfloat16 h0 = __float2bfloat16(v.x), h1 = __float2bfloat16(v.y);
    __nv_bfloat16 h2 = __float2bfloat16(v.z), h3 = __float2bfloat16(v.w);
    __nv_bfloat162 hh0, hh1, ll0, ll1;
    hh0.x = h0; hh0.y = h1; hh1.x = h2; hh1.y = h3;
    ll0.x = __float2bfloat16(v.x - __bfloat162float(h0));
    ll0.y = __float2bfloat16(v.y - __bfloat162float(h1));
    ll1.x = __float2bfloat16(v.z - __bfloat162float(h2));
    ll1.y = __float2bfloat16(v.w - __bfloat162float(h3));
    ((__nv_bfloat162*)hi)[i * 2 + 0] = hh0;
    ((__nv_bfloat162*)hi)[i * 2 + 1] = hh1;
    ((__nv_bfloat162*)lo)[i * 2 + 0] = ll0;
    ((__nv_bfloat162*)lo)[i * 2 + 1] = ll1;
}

// ---------------- tensor-core GEMM (bf16 hi/lo split, fp32-accurate) --------
__device__ __forceinline__ void mma16816(float* c, const uint32_t* a, uint32_t b0, uint32_t b1) {
    asm volatile(
        "mma.sync.aligned.m16n8k16.row.col.f32.bf16.bf16.f32 "
        "{%0,%1,%2,%3}, {%4,%5,%6,%7}, {%8,%9}, {%0,%1,%2,%3};"
        : "+f"(c[0]), "+f"(c[1]), "+f"(c[2]), "+f"(c[3])
        : "r"(a[0]), "r"(a[1]), "r"(a[2]), "r"(a[3]), "r"(b0), "r"(b1));
}

template <int K>
__global__ void gemm_bf16_k(const __nv_bfloat16* __restrict__ Ahi,
                            const __nv_bfloat16* __restrict__ Alo,
                            const float* __restrict__ W, float* __restrict__ C,
                            int nrows, int M) {
    constexpr int KP = K + 8;
    extern __shared__ __nv_bfloat16 sm[];
    __nv_bfloat16* Ah = sm;
    __nv_bfloat16* Al = Ah + 128 * KP;
    __nv_bfloat16* Bh = Al + 128 * KP;
    __nv_bfloat16* Bl = Bh + 64 * KP;

    const int r = blockIdx.z;
    const float* Wr = W + (size_t)r * K * M;
    float* Cr = C + (size_t)r * nrows * M;
    const int rowBase = blockIdx.y * 128;
    const int colBase = blockIdx.x * 64;
    const int tid = threadIdx.x;

    constexpr int CPR = K / 8;
    for (int c = tid; c < 128 * CPR; c += 256) {
        int row = c / CPR;
        int cb = c % CPR;
        int grow = rowBase + row;
        uint4 vh = make_uint4(0u, 0u, 0u, 0u), vl = vh;
        if (grow < nrows) {
            vh = *(const uint4*)(Ahi + (size_t)grow * K + cb * 8);
            vl = *(const uint4*)(Alo + (size_t)grow * K + cb * 8);
        }
        *(uint4*)&Ah[row * KP + cb * 8] = vh;
        *(uint4*)&Al[row * KP + cb * 8] = vl;
    }
    for (int idx = tid; idx < K * 64; idx += 256) {
        int k = idx >> 6, n = idx & 63;
        float v = 0.f;
        if (colBase + n < M) v = Wr[(size_t)k * M + colBase + n];
        __nv_bfloat16 h = __float2bfloat16(v);
        Bh[n * KP + k] = h;
        Bl[n * KP + k] = __float2bfloat16(v - __bfloat162float(h));
    }
    __syncthreads();

    const int warp = tid >> 5, lane = tid & 31;
    const int g = lane >> 2, t = lane & 3;
    const int mrow = warp * 16;
    const int jmax = min(8, (M - colBase + 7) / 8);

    float acc[8][4];
#pragma unroll
    for (int j = 0; j < 8; j++)
#pragma unroll
        for (int q = 0; q < 4; q++) acc[j][q] = 0.f;

    for (int ks = 0; ks < K / 16; ks++) {
        const int k0 = ks * 16;
        uint32_t ah[4], al_[4];
        const int a0 = (mrow + g) * KP + k0 + 2 * t;
        ah[0] = *(const uint32_t*)&Ah[a0];
        ah[1] = *(const uint32_t*)&Ah[a0 + 8 * KP];
        ah[2] = *(const uint32_t*)&Ah[a0 + 8];
        ah[3] = *(const uint32_t*)&Ah[a0 + 8 * KP + 8];
        al_[0] = *(const uint32_t*)&Al[a0];
        al_[1] = *(const uint32_t*)&Al[a0 + 8 * KP];
        al_[2] = *(const uint32_t*)&Al[a0 + 8];
        al_[3] = *(const uint32_t*)&Al[a0 + 8 * KP + 8];
#pragma unroll
        for (int j = 0; j < 8; j++) {
            if (j >= jmax) break;
            const int b0 = (j * 8 + g) * KP + k0 + 2 * t;
            uint32_t bh0 = *(const uint32_t*)&Bh[b0];
            uint32_t bh1 = *(const uint32_t*)&Bh[b0 + 8];
            uint32_t bl0 = *(const uint32_t*)&Bl[b0];
            uint32_t bl1 = *(const uint32_t*)&Bl[b0 + 8];
            mma16816(acc[j], ah, bh0, bh1);
            mma16816(acc[j], al_, bh0, bh1);
            mma16816(acc[j], ah, bl0, bl1);
        }
    }

    const int row0 = rowBase + mrow + g;
#pragma unroll
    for (int j = 0; j < 8; j++) {
        if (j >= jmax) break;
        int col = colBase + j * 8 + 2 * t;
        if (col + 1 < M) {
            if (row0 < nrows) {
                float2 v = make_float2(acc[j][0], acc[j][1]);
                *(float2*)(Cr + (size_t)row0 * M + col) = v;
            }
            if (row0 + 8 < nrows) {
                float2 v = make_float2(acc[j][2], acc[j][3]);
                *(float2*)(Cr + (size_t)(row0 + 8) * M + col) = v;
            }
        }
    }
}

// ---------------- attention coefficients: el/er per (r,node,head), padded *4
template <int HOUT>
__global__ void attn_k(const float* __restrict__ z, const float* __restrict__ al,
                       const float* __restrict__ ar, float* __restrict__ el,
                       float* __restrict__ er) {
    int w = (blockIdx.x * blockDim.x + threadIdx.x) >> 5;
    int lane = threadIdx.x & 31;
    if (w >= RR * NN) return;
    int r = w / NN;
    const int TOT = NH * HOUT;
    const float* zr = z + (size_t)w * TOT;
    float aL0 = 0, aL1 = 0, aL2 = 0, aR0 = 0, aR1 = 0, aR2 = 0;
    for (int j = lane; j < TOT; j += 32) {
        int h = j / HOUT, c = j % HOUT;
        float v = zr[j];
        float wl = al[((size_t)r * NH + h) * HOUT + c];
        float wr = ar[((size_t)r * NH + h) * HOUT + c];
        if (h == 0) { aL0 += v * wl; aR0 += v * wr; }
        else if (h == 1) { aL1 += v * wl; aR1 += v * wr; }
        else { aL2 += v * wl; aR2 += v * wr; }
    }
#pragma unroll
    for (int o = 16; o; o >>= 1) {
        aL0 += __shfl_xor_sync(0xffffffffu, aL0, o);
        aL1 += __shfl_xor_sync(0xffffffffu, aL1, o);
        aL2 += __shfl_xor_sync(0xffffffffu, aL2, o);
        aR0 += __shfl_xor_sync(0xffffffffu, aR0, o);
        aR1 += __shfl_xor_sync(0xffffffffu, aR1, o);
        aR2 += __shfl_xor_sync(0xffffffffu, aR2, o);
    }
    if (lane == 0) {
        size_t o = (size_t)w * 4;
        el[o] = aL0; el[o + 1] = aL1; el[o + 2] = aL2; el[o + 3] = 0.f;
        er[o] = aR0; er[o + 1] = aR1; er[o + 2] = aR2; er[o + 3] = 0.f;
    }
}

// ---------------- per-(rel,node) online softmax stats: {m, 1/s} per head ----
__global__ void stats_k(const float* __restrict__ el, const float* __restrict__ er,
                        const int* __restrict__ ptr, const int* __restrict__ csrc,
                        float* __restrict__ stats) {
    int w = (blockIdx.x * blockDim.x + threadIdx.x) >> 5;
    int lane = threadIdx.x & 31;
    if (w >= RR * NN) return;
    int r = w / NN, n = w % NN;
    const float* er4 = er + (size_t)w * 4;
    float er0 = er4[0], er1 = er4[1], er2 = er4[2];
    int beg = ptr[r * (NN + 1) + n];
    int end = ptr[r * (NN + 1) + n + 1];
    const int* cs = csrc + (size_t)r * EE;

    float m0 = -1e30f, m1 = -1e30f, m2 = -1e30f;
    float s0 = 0.f, s1 = 0.f, s2 = 0.f;
    for (int i = beg + lane; i < end; i += 32) {
        const float4 e4 = *(const float4*)(el + ((size_t)r * NN + cs[i]) * 4);
        float e0 = lrelu(e4.x + er0);
        float e1 = lrelu(e4.y + er1);
        float e2 = lrelu(e4.z + er2);
        if (e0 > m0) { s0 = s0 * __expf(m0 - e0) + 1.f; m0 = e0; } else s0 += __expf(e0 - m0);
        if (e1 > m1) { s1 = s1 * __expf(m1 - e1) + 1.f; m1 = e1; } else s1 += __expf(e1 - m1);
        if (e2 > m2) { s2 = s2 * __expf(m2 - e2) + 1.f; m2 = e2; } else s2 += __expf(e2 - m2);
    }
#pragma unroll
    for (int o = 16; o; o >>= 1) {
        float mo0 = __shfl_xor_sync(0xffffffffu, m0, o);
        float so0 = __shfl_xor_sync(0xffffffffu, s0, o);
        float mo1 = __shfl_xor_sync(0xffffffffu, m1, o);
        float so1 = __shfl_xor_sync(0xffffffffu, s1, o);
        float mo2 = __shfl_xor_sync(0xffffffffu, m2, o);
        float so2 = __shfl_xor_sync(0xffffffffu, s2, o);
        float mn;
        mn = fmaxf(m0, mo0); s0 = s0 * __expf(m0 - mn) + so0 * __expf(mo0 - mn); m0 = mn;
        mn = fmaxf(m1, mo1); s1 = s1 * __expf(m1 - mn) + so1 * __expf(mo1 - mn); m1 = mn;
        mn = fmaxf(m2, mo2); s2 = s2 * __expf(m2 - mn) + so2 * __expf(mo2 - mn); m2 = mn;
    }
    if (lane == 0) {
        float* st = stats + (size_t)w * 8;
        st[0] = m0; st[1] = m1; st[2] = m2;
        st[3] = (s0 > 0.f) ? 1.f / s0 : 0.f;
        st[4] = (s1 > 0.f) ? 1.f / s1 : 0.f;
        st[5] = (s2 > 0.f) ? 1.f / s2 : 0.f;
        st[6] = 0.f; st[7] = 0.f;
    }
}

// ---------------- edge-parallel normalized attention weights (CSR order) ----
__global__ void alpha_k(const float* __restrict__ el, const float* __restrict__ er,
                        const float* __restrict__ stats, const int* __restrict__ csrc,
                        const int* __restrict__ cdst, float* __restrict__ calpha) {
    int i = blockIdx.x * blockDim.x + threadIdx.x;
    if (i >= RR * EE) return;
    int r = i / EE;
    int s = csrc[i];
    int d = cdst[i];
    const float4 e4 = *(const float4*)(el + ((size_t)r * NN + s) * 4);
    const float4 g4 = *(const float4*)(er + ((size_t)r * NN + d) * 4);
    const float4 st0 = *(const float4*)(stats + ((size_t)r * NN + d) * 8);
    const float4 st1 = *(const float4*)(stats + ((size_t)r * NN + d) * 8 + 4);
    float a0 = __expf(lrelu(e4.x + g4.x) - st0.x) * st0.w;
    float a1 = __expf(lrelu(e4.y + g4.y) - st0.y) * st1.x;
    float a2 = __expf(lrelu(e4.z + g4.z) - st0.z) * st1.y;
    calpha[(size_t)i * 3 + 0] = a0;
    calpha[(size_t)i * 3 + 1] = a1;
    calpha[(size_t)i * 3 + 2] = a2;
}

// ---------------- aggregation: pure weighted gather, unrolled x2 ----------
template <int OUT, bool RELU>
__global__ void agg_k(const float* __restrict__ z, const float* __restrict__ calpha,
                      const float* __restrict__ bias, const int* __restrict__ ptr,
                      const int* __restrict__ csrc, float* __restrict__ out) {
    int w = (blockIdx.x * blockDim.x + threadIdx.x) >> 5;
    int lane = threadIdx.x & 31;
    if (w >= NN) return;
    const int n = w;
    const bool hiLane = (lane + 32 < OUT);
    float tot0 = 0.f, tot1 = 0.f;
    for (int r = 0; r < RR; r++) {
        int beg = ptr[r * (NN + 1) + n];
        int end = ptr[r * (NN + 1) + n + 1];
        const int* cs = csrc + (size_t)r * EE;
        const float* cal = calpha + (size_t)r * EE * 3;
        const float* zr = z + (size_t)r * NN * (NH * OUT);

        float a00 = 0, a01 = 0, a10 = 0, a11 = 0, a20 = 0, a21 = 0;
        int i = beg;
        for (; i + 1 < end; i += 2) {
            int sA = cs[i], sB = cs[i + 1];
            float b0 = cal[3 * i + 0], b1 = cal[3 * i + 1], b2 = cal[3 * i + 2];
            float c0 = cal[3 * i + 3], c1 = cal[3 * i + 4], c2 = cal[3 * i + 5];
            const float* zA = zr + (size_t)sA * (NH * OUT);
            const float* zB = zr + (size_t)sB * (NH * OUT);
            a00 += b0 * zA[0 * OUT + lane] + c0 * zB[0 * OUT + lane];
            a10 += b1 * zA[1 * OUT + lane] + c1 * zB[1 * OUT + lane];
            a20 += b2 * zA[2 * OUT + lane] + c2 * zB[2 * OUT + lane];
            if (hiLane) {
                a01 += b0 * zA[0 * OUT + lane + 32] + c0 * zB[0 * OUT + lane + 32];
                a11 += b1 * zA[1 * OUT + lane + 32] + c1 * zB[1 * OUT + lane + 32];
                a21 += b2 * zA[2 * OUT + lane + 32] + c2 * zB[2 * OUT + lane + 32];
            }
        }
        if (i < end) {
            int sA = cs[i];
            float b0 = cal[3 * i + 0], b1 = cal[3 * i + 1], b2 = cal[3 * i + 2];
            const float* zA = zr + (size_t)sA * (NH * OUT);
            a00 += b0 * zA[0 * OUT + lane];
            a10 += b1 * zA[1 * OUT + lane];
            a20 += b2 * zA[2 * OUT + lane];
            if (hiLane) {
                a01 += b0 * zA[0 * OUT + lane + 32];
                a11 += b1 * zA[1 * OUT + lane + 32];
                a21 += b2 * zA[2 * OUT + lane + 32];
            }
        }
        const float* br = bias + (size_t)r * NH * OUT;
        {
            float t0 = a00 + br[0 * OUT + lane];
            float t1 = a10 + br[1 * OUT + lane];
            float t2 = a20 + br[2 * OUT + lane];
            if (RELU) { t0 = fmaxf(t0, 0.f); t1 = fmaxf(t1, 0.f); t2 = fmaxf(t2, 0.f); }
            tot0 += (t0 + t1 + t2) * (1.f / NH);
        }
        if (hiLane) {
            float t0 = a01 + br[0 * OUT + lane + 32];
            float t1 = a11 + br[1 * OUT + lane + 32];
            float t2 = a21 + br[2 * OUT + lane + 32];
            if (RELU) { t0 = fmaxf(t0, 0.f); t1 = fmaxf(t1, 0.f); t2 = fmaxf(t2, 0.f); }
            tot1 += (t0 + t1 + t2) * (1.f / NH);
        }
    }
    out[(size_t)n * OUT + lane] = tot0 * (1.f / RR);
    if (hiLane) out[(size_t)n * OUT + lane + 32] = tot1 * (1.f / RR);
}

// ---------------- launch ----------------
extern "C" void kernel_launch(void* const* d_in, const int* in_sizes, int n_in,
                              void* d_out, int out_size) {
    const float* feat = (const float*)d_in[0];
    const int*   src  = (const int*)d_in[1];
    const int*   dst  = (const int*)d_in[2];
    const float* W1   = (const float*)d_in[3];
    const float* al1  = (const float*)d_in[4];
    const float* ar1  = (const float*)d_in[5];
    const float* b1   = (const float*)d_in[6];
    const float* W2   = (const float*)d_in[7];
    const float* al2  = (const float*)d_in[8];
    const float* ar2  = (const float*)d_in[9];
    const float* b2   = (const float*)d_in[10];
    float* out = (float*)d_out;

    unsigned char* base = nullptr;
    cudaGetSymbolAddress((void**)&base, g_scratch);

    size_t off = 0;
    auto carve = [&](size_t bytes) -> unsigned char* {
        unsigned char* p = base + off;
        off += (bytes + 255) & ~(size_t)255;
        return p;
    };
    float* z1   = (float*)carve((size_t)RR * NN * NH * FHID * 4);
    float* z2   = (float*)carve((size_t)RR * NN * NH * FC * 4);
    float* el   = (float*)carve((size_t)RR * NN * 4 * 4);   // padded *4
    float* er   = (float*)carve((size_t)RR * NN * 4 * 4);
    float* stats = (float*)carve((size_t)RR * NN * 8 * 4);
    float* calpha = (float*)carve((size_t)RR * EE * 3 * 4);
    float* hbuf = (float*)carve((size_t)NN * FHID * 4);
    int* cnt  = (int*)carve((size_t)RR * NN * 4);
    int* ptr  = (int*)carve((size_t)RR * (NN + 1) * 4);
    int* cur  = (int*)carve((size_t)RR * NN * 4);
    int* csrc = (int*)carve((size_t)RR * EE * 4);
    int* cdst = (int*)carve((size_t)RR * EE * 4);
    __nv_bfloat16* fhi = (__nv_bfloat16*)carve((size_t)NN * FIN * 2);
    __nv_bfloat16* flo = (__nv_bfloat16*)carve((size_t)NN * FIN * 2);
    __nv_bfloat16* hhi = (__nv_bfloat16*)carve((size_t)NN * FHID * 2);
    __nv_bfloat16* hlo = (__nv_bfloat16*)carve((size_t)NN * FHID * 2);

    const int SMEM1 = (2 * 128 * (FIN + 8) + 2 * 64 * (FIN + 8)) * 2;
    const int SMEM2 = (2 * 128 * (FHID + 8) + 2 * 64 * (FHID + 8)) * 2;
    cudaFuncSetAttribute(gemm_bf16_k<FIN>, cudaFuncAttributeMaxDynamicSharedMemorySize, SMEM1);
    cudaFuncSetAttribute(gemm_bf16_k<FHID>, cudaFuncAttributeMaxDynamicSharedMemorySize, SMEM2);

    // ---- CSR build (shared by both layers) ----
    zero_k<<<(RR * NN + 255) / 256, 256>>>(cnt, RR * NN);
    count_k<<<(RR * EE + 255) / 256, 256>>>(dst, cnt);
    scan_k<<<RR, 1024>>>(cnt, ptr, cur);
    scatter_k<<<(RR * EE + 255) / 256, 256>>>(src, dst, cur, csrc, cdst);

    // ---- layer 1 ----
    split_k<<<(NN * FIN / 4 + 255) / 256, 256>>>(feat, fhi, flo, NN * FIN / 4);
    {
        dim3 grid((NH * FHID + 63) / 64, (NN + 127) / 128, RR);
        gemm_bf16_k<FIN><<<grid, 256, SMEM1>>>(fhi, flo, W1, z1, NN, NH * FHID);
    }
    attn_k<FHID><<<(RR * NN * 32 + 255) / 256, 256>>>(z1, al1, ar1, el, er);
    stats_k<<<(RR * NN * 32 + 255) / 256, 256>>>(el, er, ptr, csrc, stats);
    alpha_k<<<(RR * EE + 255) / 256, 256>>>(el, er, stats, csrc, cdst, calpha);
    agg_k<FHID, true><<<(NN * 32 + 255) / 256, 256>>>(z1, calpha, b1, ptr, csrc, hbuf);

    // ---- layer 2 ----
    split_k<<<(NN * FHID / 4 + 255) / 256, 256>>>(hbuf, hhi, hlo, NN * FHID / 4);
    {
        dim3 grid((NH * FC + 63) / 64, (NN + 127) / 128, RR);
        gemm_bf16_k<FHID><<<grid, 256, SMEM2>>>(hhi, hlo, W2, z2, NN, NH * FC);
    }
    attn_k<FC><<<(RR * NN * 32 + 255) / 256, 256>>>(z2, al2, ar2, el, er);
    stats_k<<<(RR * NN * 32 + 255) / 256, 256>>>(el, er, ptr, csrc, stats);
    alpha_k<<<(RR * EE + 255) / 256, 256>>>(el, er, stats, csrc, cdst, calpha);
    agg_k<FC, false><<<(NN * 32 + 255) / 256, 256>>>(z2, calpha, b2, ptr, csrc, out);

    (void)in_sizes; (void)n_in; (void)out_size;
}

// round 4
// speedup vs baseline: 1.1750x; 1.1750x over previous
#include <cuda_runtime.h>
#include <cuda_bf16.h>
#include <cuda_fp16.h>
#include <math.h>
#include <stdint.h>

// ---------------- problem constants ----------------
#define NN   50000   // nodes
#define EE   400000  // edges per relation
#define RR   3       // relations
#define FIN  128     // input features
#define FHID 64      // hidden features
#define FC   40      // classes
#define NH   3       // heads
#define NEG_SLOPE 0.2f

#define SCRATCH_BYTES (256ull * 1024 * 1024)
__device__ __align__(256) unsigned char g_scratch[SCRATCH_BYTES];

__device__ __forceinline__ float lrelu(float x) { return x > 0.f ? x : NEG_SLOPE * x; }

// ---------------- CSR build ----------------
__global__ void zero_k(int* p, int nitems) {
    int i = blockIdx.x * blockDim.x + threadIdx.x;
    if (i < nitems) p[i] = 0;
}

__global__ void count_k(const int* __restrict__ dst, int* __restrict__ cnt) {
    int i = blockIdx.x * blockDim.x + threadIdx.x;
    if (i >= RR * EE) return;
    int r = i / EE;
    atomicAdd(&cnt[r * NN + dst[i]], 1);
}

__global__ void scan_k(const int* __restrict__ cnt, int* __restrict__ ptr, int* __restrict__ cur) {
    const int r = blockIdx.x;
    const int t = threadIdx.x;
    const int CH = (NN + 1023) / 1024;
    int s0 = t * CH;
    int s1 = s0 + CH; if (s1 > NN) s1 = NN;
    if (s0 > NN) s0 = NN;
    int sum = 0;
    for (int n = s0; n < s1; n++) sum += cnt[r * NN + n];
    __shared__ int sh[1024];
    sh[t] = sum;
    __syncthreads();
    for (int off = 1; off < 1024; off <<= 1) {
        int v = (t >= off) ? sh[t - off] : 0;
        __syncthreads();
        sh[t] += v;
        __syncthreads();
    }
    int base = sh[t] - sum;
    for (int n = s0; n < s1; n++) {
        ptr[r * (NN + 1) + n] = base;
        cur[r * NN + n] = base;
        base += cnt[r * NN + n];
    }
    if (t == 1023) ptr[r * (NN + 1) + NN] = sh[1023];
}

__global__ void scatter_k(const int* __restrict__ src, const int* __restrict__ dst,
                          int* __restrict__ cur, int* __restrict__ csrc) {
    int i = blockIdx.x * blockDim.x + threadIdx.x;
    if (i >= RR * EE) return;
    int r = i / EE;
    int d = dst[i];
    int pos = atomicAdd(&cur[r * NN + d], 1);
    csrc[(size_t)r * EE + pos] = src[i];
}

// ---------------- fp32 -> (bf16 hi, bf16 lo) split ----------------
__global__ void split_k(const float* __restrict__ in, __nv_bfloat16* __restrict__ hi,
                        __nv_bfloat16* __restrict__ lo, int n4) {
    int i = blockIdx.x * blockDim.x + threadIdx.x;
    if (i >= n4) return;
    float4 v = ((const float4*)in)[i];
    __nv_bfloat16 h0 = __float2bfloat16(v.x), h1 = __float2bfloat16(v.y);
    __nv_bfloat16 h2 = __float2bfloat16(v.z), h3 = __float2bfloat16(v.w);
    __nv_bfloat162 hh0, hh1, ll0, ll1;
    hh0.x = h0; hh0.y = h1; hh1.x = h2; hh1.y = h3;
    ll0.x = __float2bfloat16(v.x - __bfloat162float(h0));
    ll0.y = __float2bfloat16(v.y - __bfloat162float(h1));
    ll1.x = __float2bfloat16(v.z - __bfloat162float(h2));
    ll1.y = __float2bfloat16(v.w - __bfloat162float(h3));
    ((__nv_bfloat162*)hi)[i * 2 + 0] = hh0;
    ((__nv_bfloat162*)hi)[i * 2 + 1] = hh1;
    ((__nv_bfloat162*)lo)[i * 2 + 0] = ll0;
    ((__nv_bfloat162*)lo)[i * 2 + 1] = ll1;
}

// ---------------- tensor-core GEMM (bf16 hi/lo split) -> fp16 output --------
__device__ __forceinline__ void mma16816(float* c, const uint32_t* a, uint32_t b0, uint32_t b1) {
    asm volatile(
        "mma.sync.aligned.m16n8k16.row.col.f32.bf16.bf16.f32 "
        "{%0,%1,%2,%3}, {%4,%5,%6,%7}, {%8,%9}, {%0,%1,%2,%3};"
        : "+f"(c[0]), "+f"(c[1]), "+f"(c[2]), "+f"(c[3])
        : "r"(a[0]), "r"(a[1]), "r"(a[2]), "r"(a[3]), "r"(b0), "r"(b1));
}

template <int K>
__global__ void gemm_bf16_k(const __nv_bfloat16* __restrict__ Ahi,
                            const __nv_bfloat16* __restrict__ Alo,
                            const float* __restrict__ W, __half* __restrict__ C,
                            int nrows, int M) {
    constexpr int KP = K + 8;
    extern __shared__ __nv_bfloat16 sm[];
    __nv_bfloat16* Ah = sm;
    __nv_bfloat16* Al = Ah + 128 * KP;
    __nv_bfloat16* Bh = Al + 128 * KP;
    __nv_bfloat16* Bl = Bh + 64 * KP;

    const int r = blockIdx.z;
    const float* Wr = W + (size_t)r * K * M;
    __half* Cr = C + (size_t)r * nrows * M;
    const int rowBase = blockIdx.y * 128;
    const int colBase = blockIdx.x * 64;
    const int tid = threadIdx.x;

    constexpr int CPR = K / 8;
    for (int c = tid; c < 128 * CPR; c += 256) {
        int row = c / CPR;
        int cb = c % CPR;
        int grow = rowBase + row;
        uint4 vh = make_uint4(0u, 0u, 0u, 0u), vl = vh;
        if (grow < nrows) {
            vh = *(const uint4*)(Ahi + (size_t)grow * K + cb * 8);
            vl = *(const uint4*)(Alo + (size_t)grow * K + cb * 8);
        }
        *(uint4*)&Ah[row * KP + cb * 8] = vh;
        *(uint4*)&Al[row * KP + cb * 8] = vl;
    }
    for (int idx = tid; idx < K * 64; idx += 256) {
        int k = idx >> 6, n = idx & 63;
        float v = 0.f;
        if (colBase + n < M) v = Wr[(size_t)k * M + colBase + n];
        __nv_bfloat16 h = __float2bfloat16(v);
        Bh[n * KP + k] = h;
        Bl[n * KP + k] = __float2bfloat16(v - __bfloat162float(h));
    }
    __syncthreads();

    const int warp = tid >> 5, lane = tid & 31;
    const int g = lane >> 2, t = lane & 3;
    const int mrow = warp * 16;
    const int jmax = min(8, (M - colBase + 7) / 8);

    float acc[8][4];
#pragma unroll
    for (int j = 0; j < 8; j++)
#pragma unroll
        for (int q = 0; q < 4; q++) acc[j][q] = 0.f;

    for (int ks = 0; ks < K / 16; ks++) {
        const int k0 = ks * 16;
        uint32_t ah[4], al_[4];
        const int a0 = (mrow + g) * KP + k0 + 2 * t;
        ah[0] = *(const uint32_t*)&Ah[a0];
        ah[1] = *(const uint32_t*)&Ah[a0 + 8 * KP];
        ah[2] = *(const uint32_t*)&Ah[a0 + 8];
        ah[3] = *(const uint32_t*)&Ah[a0 + 8 * KP + 8];
        al_[0] = *(const uint32_t*)&Al[a0];
        al_[1] = *(const uint32_t*)&Al[a0 + 8 * KP];
        al_[2] = *(const uint32_t*)&Al[a0 + 8];
        al_[3] = *(const uint32_t*)&Al[a0 + 8 * KP + 8];
#pragma unroll
        for (int j = 0; j < 8; j++) {
            if (j >= jmax) break;
            const int b0 = (j * 8 + g) * KP + k0 + 2 * t;
            uint32_t bh0 = *(const uint32_t*)&Bh[b0];
            uint32_t bh1 = *(const uint32_t*)&Bh[b0 + 8];
            uint32_t bl0 = *(const uint32_t*)&Bl[b0];
            uint32_t bl1 = *(const uint32_t*)&Bl[b0 + 8];
            mma16816(acc[j], ah, bh0, bh1);
            mma16816(acc[j], al_, bh0, bh1);
            mma16816(acc[j], ah, bl0, bl1);
        }
    }

    const int row0 = rowBase + mrow + g;
#pragma unroll
    for (int j = 0; j < 8; j++) {
        if (j >= jmax) break;
        int col = colBase + j * 8 + 2 * t;
        if (col + 1 < M) {
            if (row0 < nrows) {
                __half2 v = __floats2half2_rn(acc[j][0], acc[j][1]);
                *(__half2*)(Cr + (size_t)row0 * M + col) = v;
            }
            if (row0 + 8 < nrows) {
                __half2 v = __floats2half2_rn(acc[j][2], acc[j][3]);
                *(__half2*)(Cr + (size_t)(row0 + 8) * M + col) = v;
            }
        }
    }
}

// ---------------- attention coefficients: el/er per (r,node,head), padded *4
template <int HOUT>
__global__ void attn_k(const __half* __restrict__ z, const float* __restrict__ al,
                       const float* __restrict__ ar, float* __restrict__ el,
                       float* __restrict__ er) {
    int w = (blockIdx.x * blockDim.x + threadIdx.x) >> 5;
    int lane = threadIdx.x & 31;
    if (w >= RR * NN) return;
    int r = w / NN;
    const int TOT = NH * HOUT;
    const __half* zr = z + (size_t)w * TOT;
    float aL0 = 0, aL1 = 0, aL2 = 0, aR0 = 0, aR1 = 0, aR2 = 0;
    for (int j = lane; j < TOT; j += 32) {
        int h = j / HOUT, c = j % HOUT;
        float v = __half2float(zr[j]);
        float wl = al[((size_t)r * NH + h) * HOUT + c];
        float wr = ar[((size_t)r * NH + h) * HOUT + c];
        if (h == 0) { aL0 += v * wl; aR0 += v * wr; }
        else if (h == 1) { aL1 += v * wl; aR1 += v * wr; }
        else { aL2 += v * wl; aR2 += v * wr; }
    }
#pragma unroll
    for (int o = 16; o; o >>= 1) {
        aL0 += __shfl_xor_sync(0xffffffffu, aL0, o);
        aL1 += __shfl_xor_sync(0xffffffffu, aL1, o);
        aL2 += __shfl_xor_sync(0xffffffffu, aL2, o);
        aR0 += __shfl_xor_sync(0xffffffffu, aR0, o);
        aR1 += __shfl_xor_sync(0xffffffffu, aR1, o);
        aR2 += __shfl_xor_sync(0xffffffffu, aR2, o);
    }
    if (lane == 0) {
        size_t o = (size_t)w * 4;
        el[o] = aL0; el[o + 1] = aL1; el[o + 2] = aL2; el[o + 3] = 0.f;
        er[o] = aR0; er[o + 1] = aR1; er[o + 2] = aR2; er[o + 3] = 0.f;
    }
}

// ------- fused: per-(rel,node) online softmax stats + normalized alphas -----
__global__ void statsalpha_k(const float* __restrict__ el, const float* __restrict__ er,
                             const int* __restrict__ ptr, const int* __restrict__ csrc,
                             float4* __restrict__ calpha) {
    int w = (blockIdx.x * blockDim.x + threadIdx.x) >> 5;
    int lane = threadIdx.x & 31;
    if (w >= RR * NN) return;
    int r = w / NN, n = w % NN;
    const float* er4 = er + (size_t)w * 4;
    float er0 = er4[0], er1 = er4[1], er2 = er4[2];
    int beg = ptr[r * (NN + 1) + n];
    int end = ptr[r * (NN + 1) + n + 1];
    if (beg == end) return;
    const int* cs = csrc + (size_t)r * EE;
    const float4* el4 = (const float4*)el + (size_t)r * NN;

    float m0 = -1e30f, m1 = -1e30f, m2 = -1e30f;
    float s0 = 0.f, s1 = 0.f, s2 = 0.f;
    for (int i = beg + lane; i < end; i += 32) {
        const float4 e4 = el4[cs[i]];
        float e0 = lrelu(e4.x + er0);
        float e1 = lrelu(e4.y + er1);
        float e2 = lrelu(e4.z + er2);
        if (e0 > m0) { s0 = s0 * __expf(m0 - e0) + 1.f; m0 = e0; } else s0 += __expf(e0 - m0);
        if (e1 > m1) { s1 = s1 * __expf(m1 - e1) + 1.f; m1 = e1; } else s1 += __expf(e1 - m1);
        if (e2 > m2) { s2 = s2 * __expf(m2 - e2) + 1.f; m2 = e2; } else s2 += __expf(e2 - m2);
    }
#pragma unroll
    for (int o = 16; o; o >>= 1) {
        float mo0 = __shfl_xor_sync(0xffffffffu, m0, o);
        float so0 = __shfl_xor_sync(0xffffffffu, s0, o);
        float mo1 = __shfl_xor_sync(0xffffffffu, m1, o);
        float so1 = __shfl_xor_sync(0xffffffffu, s1, o);
        float mo2 = __shfl_xor_sync(0xffffffffu, m2, o);
        float so2 = __shfl_xor_sync(0xffffffffu, s2, o);
        float mn;
        mn = fmaxf(m0, mo0); s0 = s0 * __expf(m0 - mn) + so0 * __expf(mo0 - mn); m0 = mn;
        mn = fmaxf(m1, mo1); s1 = s1 * __expf(m1 - mn) + so1 * __expf(mo1 - mn); m1 = mn;
        mn = fmaxf(m2, mo2); s2 = s2 * __expf(m2 - mn) + so2 * __expf(mo2 - mn); m2 = mn;
    }
    float inv0 = (s0 > 0.f) ? 1.f / s0 : 0.f;
    float inv1 = (s1 > 0.f) ? 1.f / s1 : 0.f;
    float inv2 = (s2 > 0.f) ? 1.f / s2 : 0.f;

    // pass 2: write normalized alphas (el gathers are L1/L2-warm)
    float4* ca = calpha + (size_t)r * EE;
    for (int i = beg + lane; i < end; i += 32) {
        const float4 e4 = el4[cs[i]];
        float a0 = __expf(lrelu(e4.x + er0) - m0) * inv0;
        float a1 = __expf(lrelu(e4.y + er1) - m1) * inv1;
        float a2 = __expf(lrelu(e4.z + er2) - m2) * inv2;
        ca[i] = make_float4(a0, a1, a2, 0.f);
    }
}

// ---------------- aggregation: fp16-z weighted gather, lanes own col-pairs --
// BF16OUT: write bf16 hi/lo (layer-1 hidden). else fp32 out (final).
template <int OUT, bool RELU, bool BF16OUT>
__global__ void agg_k(const __half* __restrict__ z, const float4* __restrict__ calpha,
                      const float* __restrict__ bias, const int* __restrict__ ptr,
                      const int* __restrict__ csrc, float* __restrict__ outf,
                      __nv_bfloat16* __restrict__ ohi, __nv_bfloat16* __restrict__ olo) {
    int w = (blockIdx.x * blockDim.x + threadIdx.x) >> 5;
    int lane = threadIdx.x & 31;
    if (w >= NN) return;
    const int n = w;
    constexpr int HC = OUT / 2;            // half2 columns per head-row
    const bool act = lane < HC;
    float totx = 0.f, toty = 0.f;
    for (int r = 0; r < RR; r++) {
        int beg = ptr[r * (NN + 1) + n];
        int end = ptr[r * (NN + 1) + n + 1];
        const int* cs = csrc + (size_t)r * EE;
        const float4* cal = calpha + (size_t)r * EE;
        const __half2* zr = (const __half2*)(z + (size_t)r * NN * (NH * OUT));

        float a0x = 0, a0y = 0, a1x = 0, a1y = 0, a2x = 0, a2y = 0;
        int i = beg;
        for (; i + 1 < end; i += 2) {
            int sA = cs[i], sB = cs[i + 1];
            float4 wA = cal[i], wB = cal[i + 1];
            const __half2* zA = zr + (size_t)sA * (NH * HC);
            const __half2* zB = zr + (size_t)sB * (NH * HC);
            if (act) {
                float2 v;
                v = __half22float2(zA[0 * HC + lane]); a0x += wA.x * v.x; a0y += wA.x * v.y;
                v = __half22float2(zB[0 * HC + lane]); a0x += wB.x * v.x; a0y += wB.x * v.y;
                v = __half22float2(zA[1 * HC + lane]); a1x += wA.y * v.x; a1y += wA.y * v.y;
                v = __half22float2(zB[1 * HC + lane]); a1x += wB.y * v.x; a1y += wB.y * v.y;
                v = __half22float2(zA[2 * HC + lane]); a2x += wA.z * v.x; a2y += wA.z * v.y;
                v = __half22float2(zB[2 * HC + lane]); a2x += wB.z * v.x; a2y += wB.z * v.y;
            }
        }
        if (i < end) {
            int sA = cs[i];
            float4 wA = cal[i];
            const __half2* zA = zr + (size_t)sA * (NH * HC);
            if (act) {
                float2 v;
                v = __half22float2(zA[0 * HC + lane]); a0x += wA.x * v.x; a0y += wA.x * v.y;
                v = __half22float2(zA[1 * HC + lane]); a1x += wA.y * v.x; a1y += wA.y * v.y;
                v = __half22float2(zA[2 * HC + lane]); a2x += wA.z * v.x; a2y += wA.z * v.y;
            }
        }
        if (act) {
            const float2* br = (const float2*)(bias + (size_t)r * NH * OUT);
            float2 b0 = br[0 * HC + lane], b1 = br[1 * HC + lane], b2 = br[2 * HC + lane];
            float t0x = a0x + b0.x, t0y = a0y + b0.y;
            float t1x = a1x + b1.x, t1y = a1y + b1.y;
            float t2x = a2x + b2.x, t2y = a2y + b2.y;
            if (RELU) {
                t0x = fmaxf(t0x, 0.f); t0y = fmaxf(t0y, 0.f);
                t1x = fmaxf(t1x, 0.f); t1y = fmaxf(t1y, 0.f);
                t2x = fmaxf(t2x, 0.f); t2y = fmaxf(t2y, 0.f);
            }
            totx += (t0x + t1x + t2x) * (1.f / NH);
            toty += (t0y + t1y + t2y) * (1.f / NH);
        }
    }
    if (!act) return;
    totx *= (1.f / RR);
    toty *= (1.f / RR);
    if (BF16OUT) {
        __nv_bfloat16 hx = __float2bfloat16(totx);
        __nv_bfloat16 hy = __float2bfloat16(toty);
        __nv_bfloat162 hv; hv.x = hx; hv.y = hy;
        __nv_bfloat162 lv;
        lv.x = __float2bfloat16(totx - __bfloat162float(hx));
        lv.y = __float2bfloat16(toty - __bfloat162float(hy));
        ((__nv_bfloat162*)ohi)[(size_t)n * HC + lane] = hv;
        ((__nv_bfloat162*)olo)[(size_t)n * HC + lane] = lv;
    } else {
        *(float2*)(outf + (size_t)n * OUT + 2 * lane) = make_float2(totx, toty);
    }
}

// ---------------- launch ----------------
extern "C" void kernel_launch(void* const* d_in, const int* in_sizes, int n_in,
                              void* d_out, int out_size) {
    const float* feat = (const float*)d_in[0];
    const int*   src  = (const int*)d_in[1];
    const int*   dst  = (const int*)d_in[2];
    const float* W1   = (const float*)d_in[3];
    const float* al1  = (const float*)d_in[4];
    const float* ar1  = (const float*)d_in[5];
    const float* b1   = (const float*)d_in[6];
    const float* W2   = (const float*)d_in[7];
    const float* al2  = (const float*)d_in[8];
    const float* ar2  = (const float*)d_in[9];
    const float* b2   = (const float*)d_in[10];
    float* out = (float*)d_out;

    unsigned char* base = nullptr;
    cudaGetSymbolAddress((void**)&base, g_scratch);

    size_t off = 0;
    auto carve = [&](size_t bytes) -> unsigned char* {
        unsigned char* p = base + off;
        off += (bytes + 255) & ~(size_t)255;
        return p;
    };
    __half* z1 = (__half*)carve((size_t)RR * NN * NH * FHID * 2);   // 57.6 MB
    __half* z2 = (__half*)carve((size_t)RR * NN * NH * FC * 2);     // 36 MB
    float* el   = (float*)carve((size_t)RR * NN * 4 * 4);
    float* er   = (float*)carve((size_t)RR * NN * 4 * 4);
    float4* calpha = (float4*)carve((size_t)RR * EE * 16);          // 19.2 MB
    int* cnt  = (int*)carve((size_t)RR * NN * 4);
    int* ptr  = (int*)carve((size_t)RR * (NN + 1) * 4);
    int* cur  = (int*)carve((size_t)RR * NN * 4);
    int* csrc = (int*)carve((size_t)RR * EE * 4);
    __nv_bfloat16* fhi = (__nv_bfloat16*)carve((size_t)NN * FIN * 2);
    __nv_bfloat16* flo = (__nv_bfloat16*)carve((size_t)NN * FIN * 2);
    __nv_bfloat16* hhi = (__nv_bfloat16*)carve((size_t)NN * FHID * 2);
    __nv_bfloat16* hlo = (__nv_bfloat16*)carve((size_t)NN * FHID * 2);

    const int SMEM1 = (2 * 128 * (FIN + 8) + 2 * 64 * (FIN + 8)) * 2;
    const int SMEM2 = (2 * 128 * (FHID + 8) + 2 * 64 * (FHID + 8)) * 2;
    cudaFuncSetAttribute(gemm_bf16_k<FIN>, cudaFuncAttributeMaxDynamicSharedMemorySize, SMEM1);
    cudaFuncSetAttribute(gemm_bf16_k<FHID>, cudaFuncAttributeMaxDynamicSharedMemorySize, SMEM2);

    // ---- CSR build (shared by both layers) ----
    zero_k<<<(RR * NN + 255) / 256, 256>>>(cnt, RR * NN);
    count_k<<<(RR * EE + 255) / 256, 256>>>(dst, cnt);
    scan_k<<<RR, 1024>>>(cnt, ptr, cur);
    scatter_k<<<(RR * EE + 255) / 256, 256>>>(src, dst, cur, csrc);

    // ---- layer 1 ----
    split_k<<<(NN * FIN / 4 + 255) / 256, 256>>>(feat, fhi, flo, NN * FIN / 4);
    {
        dim3 grid((NH * FHID + 63) / 64, (NN + 127) / 128, RR);
        gemm_bf16_k<FIN><<<grid, 256, SMEM1>>>(fhi, flo, W1, z1, NN, NH * FHID);
    }
    attn_k<FHID><<<(RR * NN * 32 + 255) / 256, 256>>>(z1, al1, ar1, el, er);
    statsalpha_k<<<(RR * NN * 32 + 255) / 256, 256>>>(el, er, ptr, csrc, calpha);
    agg_k<FHID, true, true><<<(NN * 32 + 255) / 256, 256>>>(z1, calpha, b1, ptr, csrc,
                                                            nullptr, hhi, hlo);

    // ---- layer 2 ----
    {
        dim3 grid((NH * FC + 63) / 64, (NN + 127) / 128, RR);
        gemm_bf16_k<FHID><<<grid, 256, SMEM2>>>(hhi, hlo, W2, z2, NN, NH * FC);
    }
    attn_k<FC><<<(RR * NN * 32 + 255) / 256, 256>>>(z2, al2, ar2, el, er);
    statsalpha_k<<<(RR * NN * 32 + 255) / 256, 256>>>(el, er, ptr, csrc, calpha);
    agg_k<FC, false, false><<<(NN * 32 + 255) / 256, 256>>>(z2, calpha, b2, ptr, csrc,
                                                            out, nullptr, nullptr);

    (void)in_sizes; (void)n_in; (void)out_size;
}

// round 5
// speedup vs baseline: 1.3584x; 1.1562x over previous
#include <cuda_runtime.h>
#include <cuda_bf16.h>
#include <cuda_fp16.h>
#include <math.h>
#include <stdint.h>

// ---------------- problem constants ----------------
#define NN   50000   // nodes
#define EE   400000  // edges per relation
#define RR   3       // relations
#define FIN  128     // input features
#define FHID 64      // hidden features
#define FC   40      // classes
#define NH   3       // heads
#define NEG_SLOPE 0.2f

#define SCRATCH_BYTES (256ull * 1024 * 1024)
__device__ __align__(256) unsigned char g_scratch[SCRATCH_BYTES];

__device__ __forceinline__ float lrelu(float x) { return x > 0.f ? x : NEG_SLOPE * x; }

// ---------------- CSR build ----------------
__global__ void zero_k(int* p, int nitems) {
    int i = blockIdx.x * blockDim.x + threadIdx.x;
    if (i < nitems) p[i] = 0;
}

__global__ void count_k(const int* __restrict__ dst, int* __restrict__ cnt) {
    int i = blockIdx.x * blockDim.x + threadIdx.x;
    if (i >= RR * EE) return;
    int r = i / EE;
    atomicAdd(&cnt[r * NN + dst[i]], 1);
}

__global__ void scan_k(const int* __restrict__ cnt, int* __restrict__ ptr, int* __restrict__ cur) {
    const int r = blockIdx.x;
    const int t = threadIdx.x;
    const int CH = (NN + 1023) / 1024;
    int s0 = t * CH;
    int s1 = s0 + CH; if (s1 > NN) s1 = NN;
    if (s0 > NN) s0 = NN;
    int sum = 0;
    for (int n = s0; n < s1; n++) sum += cnt[r * NN + n];
    __shared__ int sh[1024];
    sh[t] = sum;
    __syncthreads();
    for (int off = 1; off < 1024; off <<= 1) {
        int v = (t >= off) ? sh[t - off] : 0;
        __syncthreads();
        sh[t] += v;
        __syncthreads();
    }
    int base = sh[t] - sum;
    for (int n = s0; n < s1; n++) {
        ptr[r * (NN + 1) + n] = base;
        cur[r * NN + n] = base;
        base += cnt[r * NN + n];
    }
    if (t == 1023) ptr[r * (NN + 1) + NN] = sh[1023];
}

__global__ void scatter_k(const int* __restrict__ src, const int* __restrict__ dst,
                          int* __restrict__ cur, int* __restrict__ csrc) {
    int i = blockIdx.x * blockDim.x + threadIdx.x;
    if (i >= RR * EE) return;
    int r = i / EE;
    int d = dst[i];
    int pos = atomicAdd(&cur[r * NN + d], 1);
    csrc[(size_t)r * EE + pos] = src[i];
}

// ---------------- fp32 -> (bf16 hi, bf16 lo) split ----------------
__global__ void split_k(const float* __restrict__ in, __nv_bfloat16* __restrict__ hi,
                        __nv_bfloat16* __restrict__ lo, int n4) {
    int i = blockIdx.x * blockDim.x + threadIdx.x;
    if (i >= n4) return;
    float4 v = ((const float4*)in)[i];
    __nv_bfloat16 h0 = __float2bfloat16(v.x), h1 = __float2bfloat16(v.y);
    __nv_bfloat16 h2 = __float2bfloat16(v.z), h3 = __float2bfloat16(v.w);
    __nv_bfloat162 hh0, hh1, ll0, ll1;
    hh0.x = h0; hh0.y = h1; hh1.x = h2; hh1.y = h3;
    ll0.x = __float2bfloat16(v.x - __bfloat162float(h0));
    ll0.y = __float2bfloat16(v.y - __bfloat162float(h1));
    ll1.x = __float2bfloat16(v.z - __bfloat162float(h2));
    ll1.y = __float2bfloat16(v.w - __bfloat162float(h3));
    ((__nv_bfloat162*)hi)[i * 2 + 0] = hh0;
    ((__nv_bfloat162*)hi)[i * 2 + 1] = hh1;
    ((__nv_bfloat162*)lo)[i * 2 + 0] = ll0;
    ((__nv_bfloat162*)lo)[i * 2 + 1] = ll1;
}

// ------- tensor-core GEMM (bf16 hi/lo split) -> fp16 z, fused el/er epilogue
// Column block == one attention head (BN = head width). M = NH*BN exactly.
__device__ __forceinline__ void mma16816(float* c, const uint32_t* a, uint32_t b0, uint32_t b1) {
    asm volatile(
        "mma.sync.aligned.m16n8k16.row.col.f32.bf16.bf16.f32 "
        "{%0,%1,%2,%3}, {%4,%5,%6,%7}, {%8,%9}, {%0,%1,%2,%3};"
        : "+f"(c[0]), "+f"(c[1]), "+f"(c[2]), "+f"(c[3])
        : "r"(a[0]), "r"(a[1]), "r"(a[2]), "r"(a[3]), "r"(b0), "r"(b1));
}

template <int K, int BN>
__global__ void gemm_attn_k(const __nv_bfloat16* __restrict__ Ahi,
                            const __nv_bfloat16* __restrict__ Alo,
                            const float* __restrict__ W,
                            const float* __restrict__ alw,
                            const float* __restrict__ arw,
                            __half* __restrict__ C,
                            float* __restrict__ el, float* __restrict__ er,
                            int nrows) {
    constexpr int KP = K + 8;
    constexpr int M = NH * BN;
    constexpr int JN = BN / 8;
    extern __shared__ __nv_bfloat16 sm[];
    __nv_bfloat16* Ah = sm;
    __nv_bfloat16* Al = Ah + 128 * KP;
    __nv_bfloat16* Bh = Al + 128 * KP;
    __nv_bfloat16* Bl = Bh + BN * KP;

    const int r = blockIdx.z;
    const int head = blockIdx.x;
    const int colBase = head * BN;
    const float* Wr = W + (size_t)r * K * M;
    __half* Cr = C + (size_t)r * nrows * M;
    const int rowBase = blockIdx.y * 128;
    const int tid = threadIdx.x;

    constexpr int CPR = K / 8;
    for (int c = tid; c < 128 * CPR; c += 256) {
        int row = c / CPR;
        int cb = c % CPR;
        int grow = rowBase + row;
        uint4 vh = make_uint4(0u, 0u, 0u, 0u), vl = vh;
        if (grow < nrows) {
            vh = *(const uint4*)(Ahi + (size_t)grow * K + cb * 8);
            vl = *(const uint4*)(Alo + (size_t)grow * K + cb * 8);
        }
        *(uint4*)&Ah[row * KP + cb * 8] = vh;
        *(uint4*)&Al[row * KP + cb * 8] = vl;
    }
    for (int idx = tid; idx < K * BN; idx += 256) {
        int k = idx / BN, n = idx % BN;
        float v = Wr[(size_t)k * M + colBase + n];
        __nv_bfloat16 h = __float2bfloat16(v);
        Bh[n * KP + k] = h;
        Bl[n * KP + k] = __float2bfloat16(v - __bfloat162float(h));
    }
    __syncthreads();

    const int warp = tid >> 5, lane = tid & 31;
    const int g = lane >> 2, t = lane & 3;
    const int mrow = warp * 16;

    float acc[JN][4];
#pragma unroll
    for (int j = 0; j < JN; j++)
#pragma unroll
        for (int q = 0; q < 4; q++) acc[j][q] = 0.f;

    for (int ks = 0; ks < K / 16; ks++) {
        const int k0 = ks * 16;
        uint32_t ah[4], al_[4];
        const int a0 = (mrow + g) * KP + k0 + 2 * t;
        ah[0] = *(const uint32_t*)&Ah[a0];
        ah[1] = *(const uint32_t*)&Ah[a0 + 8 * KP];
        ah[2] = *(const uint32_t*)&Ah[a0 + 8];
        ah[3] = *(const uint32_t*)&Ah[a0 + 8 * KP + 8];
        al_[0] = *(const uint32_t*)&Al[a0];
        al_[1] = *(const uint32_t*)&Al[a0 + 8 * KP];
        al_[2] = *(const uint32_t*)&Al[a0 + 8];
        al_[3] = *(const uint32_t*)&Al[a0 + 8 * KP + 8];
#pragma unroll
        for (int j = 0; j < JN; j++) {
            const int b0 = (j * 8 + g) * KP + k0 + 2 * t;
            uint32_t bh0 = *(const uint32_t*)&Bh[b0];
            uint32_t bh1 = *(const uint32_t*)&Bh[b0 + 8];
            uint32_t bl0 = *(const uint32_t*)&Bl[b0];
            uint32_t bl1 = *(const uint32_t*)&Bl[b0 + 8];
            mma16816(acc[j], ah, bh0, bh1);
            mma16816(acc[j], al_, bh0, bh1);
            mma16816(acc[j], ah, bl0, bl1);
        }
    }

    // store z (fp16)
    const int row0 = rowBase + mrow + g;
#pragma unroll
    for (int j = 0; j < JN; j++) {
        int col = colBase + j * 8 + 2 * t;
        if (row0 < nrows) {
            __half2 v = __floats2half2_rn(acc[j][0], acc[j][1]);
            *(__half2*)(Cr + (size_t)row0 * M + col) = v;
        }
        if (row0 + 8 < nrows) {
            __half2 v = __floats2half2_rn(acc[j][2], acc[j][3]);
            *(__half2*)(Cr + (size_t)(row0 + 8) * M + col) = v;
        }
    }

    // fused el/er epilogue: dot fp32 accs with al/ar for this head
    const float* alr = alw + ((size_t)r * NH + head) * BN;
    const float* arr = arw + ((size_t)r * NH + head) * BN;
    float pel0 = 0.f, pel1 = 0.f, per0 = 0.f, per1 = 0.f;
#pragma unroll
    for (int j = 0; j < JN; j++) {
        int c0 = j * 8 + 2 * t;
        float w0 = alr[c0], w1 = alr[c0 + 1];
        float v0 = arr[c0], v1 = arr[c0 + 1];
        pel0 += acc[j][0] * w0 + acc[j][1] * w1;
        pel1 += acc[j][2] * w0 + acc[j][3] * w1;
        per0 += acc[j][0] * v0 + acc[j][1] * v1;
        per1 += acc[j][2] * v0 + acc[j][3] * v1;
    }
#pragma unroll
    for (int o = 1; o <= 2; o <<= 1) {
        pel0 += __shfl_xor_sync(0xffffffffu, pel0, o);
        pel1 += __shfl_xor_sync(0xffffffffu, pel1, o);
        per0 += __shfl_xor_sync(0xffffffffu, per0, o);
        per1 += __shfl_xor_sync(0xffffffffu, per1, o);
    }
    if (t == 0) {
        if (row0 < nrows) {
            el[((size_t)r * NN + row0) * 4 + head] = pel0;
            er[((size_t)r * NN + row0) * 4 + head] = per0;
        }
        if (row0 + 8 < nrows) {
            el[((size_t)r * NN + row0 + 8) * 4 + head] = pel1;
            er[((size_t)r * NN + row0 + 8) * 4 + head] = per1;
        }
    }
}

// ------- per-(rel,node): max pass + unnormalized alpha + 1/s --------------
__global__ void statsalpha_k(const float* __restrict__ el, const float* __restrict__ er,
                             const int* __restrict__ ptr, const int* __restrict__ csrc,
                             float4* __restrict__ calpha, float4* __restrict__ inv4) {
    int w = (blockIdx.x * blockDim.x + threadIdx.x) >> 5;
    int lane = threadIdx.x & 31;
    if (w >= RR * NN) return;
    int r = w / NN, n = w % NN;
    int beg = ptr[r * (NN + 1) + n];
    int end = ptr[r * (NN + 1) + n + 1];
    if (beg == end) {
        if (lane == 0) inv4[w] = make_float4(0.f, 0.f, 0.f, 0.f);
        return;
    }
    const float* er4 = er + (size_t)w * 4;
    float er0 = er4[0], er1 = er4[1], er2 = er4[2];
    const int* cs = csrc + (size_t)r * EE;
    const float4* el4 = (const float4*)el + (size_t)r * NN;

    // pass 1: plain max (no exp)
    float m0 = -1e30f, m1 = -1e30f, m2 = -1e30f;
    for (int i = beg + lane; i < end; i += 32) {
        const float4 e4 = el4[cs[i]];
        m0 = fmaxf(m0, lrelu(e4.x + er0));
        m1 = fmaxf(m1, lrelu(e4.y + er1));
        m2 = fmaxf(m2, lrelu(e4.z + er2));
    }
#pragma unroll
    for (int o = 16; o; o >>= 1) {
        m0 = fmaxf(m0, __shfl_xor_sync(0xffffffffu, m0, o));
        m1 = fmaxf(m1, __shfl_xor_sync(0xffffffffu, m1, o));
        m2 = fmaxf(m2, __shfl_xor_sync(0xffffffffu, m2, o));
    }
    // pass 2: exp once, store unnormalized alpha, accumulate s
    float s0 = 0.f, s1 = 0.f, s2 = 0.f;
    float4* ca = calpha + (size_t)r * EE;
    for (int i = beg + lane; i < end; i += 32) {
        const float4 e4 = el4[cs[i]];
        float a0 = __expf(lrelu(e4.x + er0) - m0);
        float a1 = __expf(lrelu(e4.y + er1) - m1);
        float a2 = __expf(lrelu(e4.z + er2) - m2);
        s0 += a0; s1 += a1; s2 += a2;
        ca[i] = make_float4(a0, a1, a2, 0.f);
    }
#pragma unroll
    for (int o = 16; o; o >>= 1) {
        s0 += __shfl_xor_sync(0xffffffffu, s0, o);
        s1 += __shfl_xor_sync(0xffffffffu, s1, o);
        s2 += __shfl_xor_sync(0xffffffffu, s2, o);
    }
    if (lane == 0)
        inv4[w] = make_float4(1.f / s0, 1.f / s1, 1.f / s2, 0.f);
}

// ---------------- aggregation: fp16-z weighted gather, scale by 1/s --------
template <int OUT, bool RELU, bool BF16OUT>
__global__ void agg_k(const __half* __restrict__ z, const float4* __restrict__ calpha,
                      const float4* __restrict__ inv4, const float* __restrict__ bias,
                      const int* __restrict__ ptr, const int* __restrict__ csrc,
                      float* __restrict__ outf,
                      __nv_bfloat16* __restrict__ ohi, __nv_bfloat16* __restrict__ olo) {
    int w = (blockIdx.x * blockDim.x + threadIdx.x) >> 5;
    int lane = threadIdx.x & 31;
    if (w >= NN) return;
    const int n = w;
    constexpr int HC = OUT / 2;
    const bool act = lane < HC;
    float totx = 0.f, toty = 0.f;
    for (int r = 0; r < RR; r++) {
        int beg = ptr[r * (NN + 1) + n];
        int end = ptr[r * (NN + 1) + n + 1];
        const int* cs = csrc + (size_t)r * EE;
        const float4* cal = calpha + (size_t)r * EE;
        const __half2* zr = (const __half2*)(z + (size_t)r * NN * (NH * OUT));
        const float4 inv = inv4[(size_t)r * NN + n];

        float a0x = 0, a0y = 0, a1x = 0, a1y = 0, a2x = 0, a2y = 0;
        int i = beg;
        for (; i + 1 < end; i += 2) {
            int sA = cs[i], sB = cs[i + 1];
            float4 wA = cal[i], wB = cal[i + 1];
            const __half2* zA = zr + (size_t)sA * (NH * HC);
            const __half2* zB = zr + (size_t)sB * (NH * HC);
            if (act) {
                float2 v;
                v = __half22float2(zA[0 * HC + lane]); a0x += wA.x * v.x; a0y += wA.x * v.y;
                v = __half22float2(zB[0 * HC + lane]); a0x += wB.x * v.x; a0y += wB.x * v.y;
                v = __half22float2(zA[1 * HC + lane]); a1x += wA.y * v.x; a1y += wA.y * v.y;
                v = __half22float2(zB[1 * HC + lane]); a1x += wB.y * v.x; a1y += wB.y * v.y;
                v = __half22float2(zA[2 * HC + lane]); a2x += wA.z * v.x; a2y += wA.z * v.y;
                v = __half22float2(zB[2 * HC + lane]); a2x += wB.z * v.x; a2y += wB.z * v.y;
            }
        }
        if (i < end) {
            int sA = cs[i];
            float4 wA = cal[i];
            const __half2* zA = zr + (size_t)sA * (NH * HC);
            if (act) {
                float2 v;
                v = __half22float2(zA[0 * HC + lane]); a0x += wA.x * v.x; a0y += wA.x * v.y;
                v = __half22float2(zA[1 * HC + lane]); a1x += wA.y * v.x; a1y += wA.y * v.y;
                v = __half22float2(zA[2 * HC + lane]); a2x += wA.z * v.x; a2y += wA.z * v.y;
            }
        }
        if (act) {
            const float2* br = (const float2*)(bias + (size_t)r * NH * OUT);
            float2 b0 = br[0 * HC + lane], b1 = br[1 * HC + lane], b2 = br[2 * HC + lane];
            float t0x = a0x * inv.x + b0.x, t0y = a0y * inv.x + b0.y;
            float t1x = a1x * inv.y + b1.x, t1y = a1y * inv.y + b1.y;
            float t2x = a2x * inv.z + b2.x, t2y = a2y * inv.z + b2.y;
            if (RELU) {
                t0x = fmaxf(t0x, 0.f); t0y = fmaxf(t0y, 0.f);
                t1x = fmaxf(t1x, 0.f); t1y = fmaxf(t1y, 0.f);
                t2x = fmaxf(t2x, 0.f); t2y = fmaxf(t2y, 0.f);
            }
            totx += (t0x + t1x + t2x) * (1.f / NH);
            toty += (t0y + t1y + t2y) * (1.f / NH);
        }
    }
    if (!act) return;
    totx *= (1.f / RR);
    toty *= (1.f / RR);
    if (BF16OUT) {
        __nv_bfloat16 hx = __float2bfloat16(totx);
        __nv_bfloat16 hy = __float2bfloat16(toty);
        __nv_bfloat162 hv; hv.x = hx; hv.y = hy;
        __nv_bfloat162 lv;
        lv.x = __float2bfloat16(totx - __bfloat162float(hx));
        lv.y = __float2bfloat16(toty - __bfloat162float(hy));
        ((__nv_bfloat162*)ohi)[(size_t)n * HC + lane] = hv;
        ((__nv_bfloat162*)olo)[(size_t)n * HC + lane] = lv;
    } else {
        *(float2*)(outf + (size_t)n * OUT + 2 * lane) = make_float2(totx, toty);
    }
}

// ---------------- launch ----------------
extern "C" void kernel_launch(void* const* d_in, const int* in_sizes, int n_in,
                              void* d_out, int out_size) {
    const float* feat = (const float*)d_in[0];
    const int*   src  = (const int*)d_in[1];
    const int*   dst  = (const int*)d_in[2];
    const float* W1   = (const float*)d_in[3];
    const float* al1  = (const float*)d_in[4];
    const float* ar1  = (const float*)d_in[5];
    const float* b1   = (const float*)d_in[6];
    const float* W2   = (const float*)d_in[7];
    const float* al2  = (const float*)d_in[8];
    const float* ar2  = (const float*)d_in[9];
    const float* b2   = (const float*)d_in[10];
    float* out = (float*)d_out;

    unsigned char* base = nullptr;
    cudaGetSymbolAddress((void**)&base, g_scratch);

    size_t off = 0;
    auto carve = [&](size_t bytes) -> unsigned char* {
        unsigned char* p = base + off;
        off += (bytes + 255) & ~(size_t)255;
        return p;
    };
    __half* z1 = (__half*)carve((size_t)RR * NN * NH * FHID * 2);
    __half* z2 = (__half*)carve((size_t)RR * NN * NH * FC * 2);
    float* el   = (float*)carve((size_t)RR * NN * 4 * 4);
    float* er   = (float*)carve((size_t)RR * NN * 4 * 4);
    float4* inv4 = (float4*)carve((size_t)RR * NN * 16);
    float4* calpha = (float4*)carve((size_t)RR * EE * 16);
    int* cnt  = (int*)carve((size_t)RR * NN * 4);
    int* ptr  = (int*)carve((size_t)RR * (NN + 1) * 4);
    int* cur  = (int*)carve((size_t)RR * NN * 4);
    int* csrc = (int*)carve((size_t)RR * EE * 4);
    __nv_bfloat16* fhi = (__nv_bfloat16*)carve((size_t)NN * FIN * 2);
    __nv_bfloat16* flo = (__nv_bfloat16*)carve((size_t)NN * FIN * 2);
    __nv_bfloat16* hhi = (__nv_bfloat16*)carve((size_t)NN * FHID * 2);
    __nv_bfloat16* hlo = (__nv_bfloat16*)carve((size_t)NN * FHID * 2);

    const int SMEM1 = (2 * 128 * (FIN + 8) + 2 * 64 * (FIN + 8)) * 2;   // K=128,BN=64
    const int SMEM2 = (2 * 128 * (FHID + 8) + 2 * 40 * (FHID + 8)) * 2; // K=64, BN=40
    cudaFuncSetAttribute((const void*)gemm_attn_k<FIN, 64>,
                         cudaFuncAttributeMaxDynamicSharedMemorySize, SMEM1);
    cudaFuncSetAttribute((const void*)gemm_attn_k<FHID, 40>,
                         cudaFuncAttributeMaxDynamicSharedMemorySize, SMEM2);

    // ---- CSR build (shared by both layers) ----
    zero_k<<<(RR * NN + 255) / 256, 256>>>(cnt, RR * NN);
    count_k<<<(RR * EE + 255) / 256, 256>>>(dst, cnt);
    scan_k<<<RR, 1024>>>(cnt, ptr, cur);
    scatter_k<<<(RR * EE + 255) / 256, 256>>>(src, dst, cur, csrc);

    // ---- layer 1 ----
    split_k<<<(NN * FIN / 4 + 255) / 256, 256>>>(feat, fhi, flo, NN * FIN / 4);
    {
        dim3 grid(NH, (NN + 127) / 128, RR);
        gemm_attn_k<FIN, 64><<<grid, 256, SMEM1>>>(fhi, flo, W1, al1, ar1, z1, el, er, NN);
    }
    statsalpha_k<<<(RR * NN * 32 + 255) / 256, 256>>>(el, er, ptr, csrc, calpha, inv4);
    agg_k<FHID, true, true><<<(NN * 32 + 255) / 256, 256>>>(z1, calpha, inv4, b1, ptr, csrc,
                                                            nullptr, hhi, hlo);

    // ---- layer 2 ----
    {
        dim3 grid(NH, (NN + 127) / 128, RR);
        gemm_attn_k<FHID, 40><<<grid, 256, SMEM2>>>(hhi, hlo, W2, al2, ar2, z2, el, er, NN);
    }
    statsalpha_k<<<(RR * NN * 32 + 255) / 256, 256>>>(el, er, ptr, csrc, calpha, inv4);
    agg_k<FC, false, false><<<(NN * 32 + 255) / 256, 256>>>(z2, calpha, inv4, b2, ptr, csrc,
                                                            out, nullptr, nullptr);

    (void)in_sizes; (void)n_in; (void)out_size;
}